// round 6
// baseline (speedup 1.0000x reference)
#include <cuda_runtime.h>
#include <cuda_fp16.h>
#include <math.h>

#define N_NODES 100000
#define N_EDGES 1600000
#define NB_SCAN 391   // ceil(100000/256)
#define AGG_BLOCKS 592

// ---------------- scratch (device globals) ----------------
__device__ float  g_h1[(size_t)N_NODES * 64];   // tanh MLP branch (fp32)
__device__ __half g_xs[(size_t)N_NODES * 64];   // filter linear out * inv_out (fp16)
__device__ float  g_h2[(size_t)N_NODES * 64];   // aggregated branch (inv_in applied)
__device__ int    g_deg_out[N_NODES];
__device__ int    g_deg_in [N_NODES];
__device__ float  g_inv_out[N_NODES];
__device__ int    g_rowstart[N_NODES];
__device__ int    g_cursor[N_NODES];
__device__ int    g_part[512];
__device__ int    g_csr[N_EDGES];
__device__ float  g_W[64 * 128];                // fused [k][j]: j<64 fc1, j>=64 filt
__device__ float  g_bias[128];
__device__ float  g_wpart[2][16];               // attention logit partial sums

__device__ __forceinline__ float fast_tanh(float x) {
    float e = __expf(2.f * x);
    return 1.f - __fdividef(2.f, e + 1.f);
}

// ---- packed f32x2 helpers (sm_103a) ----
__device__ __forceinline__ unsigned long long pack2(float lo, float hi) {
    unsigned long long r;
    asm("mov.b64 %0, {%1, %2};" : "=l"(r) : "f"(lo), "f"(hi));
    return r;
}
__device__ __forceinline__ float2 unpack2(unsigned long long v) {
    float2 r;
    asm("mov.b64 {%0, %1}, %2;" : "=f"(r.x), "=f"(r.y) : "l"(v));
    return r;
}
__device__ __forceinline__ void fma2(unsigned long long& d, unsigned long long a,
                                     unsigned long long b) {
    asm("fma.rn.f32x2 %0, %1, %2, %0;" : "+l"(d) : "l"(a), "l"(b));
}

// ---------------- zero scratch ----------------
__global__ void k_init() {
    int i = blockIdx.x * blockDim.x + threadIdx.x;
    if (i < N_NODES) { g_deg_out[i] = 0; g_deg_in[i] = 0; }
    if (i < 32) g_wpart[i >> 4][i & 15] = 0.f;
}

// ---------------- degree histogram (4 edges / thread) ----------------
__global__ void k_degree(const int4* __restrict__ src4, const int4* __restrict__ dst4) {
    int i = blockIdx.x * blockDim.x + threadIdx.x;
    if (i >= N_EDGES / 4) return;
    int4 s = __ldg(&src4[i]);
    int4 d = __ldg(&dst4[i]);
    atomicAdd(&g_deg_out[s.x], 1); atomicAdd(&g_deg_out[s.y], 1);
    atomicAdd(&g_deg_out[s.z], 1); atomicAdd(&g_deg_out[s.w], 1);
    atomicAdd(&g_deg_in[d.x], 1);  atomicAdd(&g_deg_in[d.y], 1);
    atomicAdd(&g_deg_in[d.z], 1);  atomicAdd(&g_deg_in[d.w], 1);
}

// ---------------- inv_out + fused weight prep (side stream) ----------------
__global__ void k_prep(const float* __restrict__ fc1_w, const float* __restrict__ fc1_b,
                       const float* __restrict__ filt_w, const float* __restrict__ filt_b) {
    int i = blockIdx.x * blockDim.x + threadIdx.x;
    if (i < N_NODES) g_inv_out[i] = rsqrtf(fmaxf((float)g_deg_out[i], 1.f));
    if (i < 64 * 128) {
        int k = i >> 7, j = i & 127;
        g_W[i] = (j < 64) ? fc1_w[j * 64 + k] : filt_w[(j - 64) * 64 + k];
    }
    if (i < 128) g_bias[i] = (i < 64) ? fc1_b[i] : filt_b[i - 64];
}

// ---------------- exclusive scan of deg_in (3 stages) ----------------
__global__ void k_scan1() {
    __shared__ int sh[256];
    int t = threadIdx.x;
    int i = blockIdx.x * 256 + t;
    int v = (i < N_NODES) ? g_deg_in[i] : 0;
    sh[t] = v;
    __syncthreads();
#pragma unroll
    for (int off = 1; off < 256; off <<= 1) {
        int add = (t >= off) ? sh[t - off] : 0;
        __syncthreads();
        sh[t] += add;
        __syncthreads();
    }
    if (i < N_NODES) g_rowstart[i] = sh[t] - v;
    if (t == 255) g_part[blockIdx.x] = sh[255];
}

__global__ void k_scan2() {
    __shared__ int sh[512];
    int t = threadIdx.x;
    int v = (t < NB_SCAN) ? g_part[t] : 0;
    sh[t] = v;
    __syncthreads();
#pragma unroll
    for (int off = 1; off < 512; off <<= 1) {
        int add = (t >= off) ? sh[t - off] : 0;
        __syncthreads();
        sh[t] += add;
        __syncthreads();
    }
    if (t < NB_SCAN) g_part[t] = sh[t] - v;
}

__global__ void k_scan3() {
    int i = blockIdx.x * blockDim.x + threadIdx.x;
    if (i < N_NODES) {
        int rs = g_rowstart[i] + g_part[i >> 8];
        g_rowstart[i] = rs;
        g_cursor[i]   = rs;
    }
}

// ---------------- CSR build (counting sort by dst) ----------------
__global__ void k_csr(const int* __restrict__ src, const int* __restrict__ dst) {
    int e = blockIdx.x * blockDim.x + threadIdx.x;
    if (e >= N_EDGES) return;
    int d = __ldg(&dst[e]);
    int pos = atomicAdd(&g_cursor[d], 1);
    g_csr[pos] = __ldg(&src[e]);
}

// ---------------- tiled dual GEMM: 512 thr, 4x8 f32x2 tile, 50% occupancy ----------------
__global__ __launch_bounds__(512, 2) void k_gemm(const float* __restrict__ feat) {
    __shared__ float Bs[64][128];     // 32KB
    __shared__ float As[16][128];     // 8KB
    __shared__ float bias_s[128];

    int tid = threadIdx.x;
    int m0 = blockIdx.x * 128;

    for (int i = tid; i < 64 * 128; i += 512) ((float*)Bs)[i] = g_W[i];
    if (tid < 128) bias_s[tid] = g_bias[tid];

    int tx = tid & 15, ty = tid >> 4;     // tx: 16 col-groups of 8, ty: 32 node-groups of 4
    int r  = tid & 127, q = tid >> 7;     // staging: row r, k-quad q (0..3)

    unsigned long long acc[4][4];   // 4 nodes x 4 f32x2 pairs (8 cols)
#pragma unroll
    for (int i = 0; i < 4; i++)
#pragma unroll
        for (int j = 0; j < 4; j++) acc[i][j] = 0ull;

    int m_load = m0 + r;
    bool valid = m_load < N_NODES;
    const float4* frow = reinterpret_cast<const float4*>(feat + (size_t)m_load * 64);
    float4 z4 = make_float4(0.f, 0.f, 0.f, 0.f);

    for (int kc = 0; kc < 64; kc += 16) {
        __syncthreads();
        float4 v = valid ? frow[(kc >> 2) + q] : z4;
        int kb = q * 4;
        As[kb + 0][r] = v.x; As[kb + 1][r] = v.y;
        As[kb + 2][r] = v.z; As[kb + 3][r] = v.w;
        __syncthreads();

#pragma unroll
        for (int k = 0; k < 16; k++) {
            float4 a4 = *reinterpret_cast<const float4*>(&As[k][ty * 4]);
            ulonglong2 b01 = *reinterpret_cast<const ulonglong2*>(&Bs[kc + k][tx * 8]);
            ulonglong2 b23 = *reinterpret_cast<const ulonglong2*>(&Bs[kc + k][tx * 8 + 4]);
            unsigned long long bp[4] = {b01.x, b01.y, b23.x, b23.y};
            float a[4] = {a4.x, a4.y, a4.z, a4.w};
#pragma unroll
            for (int i = 0; i < 4; i++) {
                unsigned long long ai = pack2(a[i], a[i]);
#pragma unroll
                for (int j = 0; j < 4; j++) fma2(acc[i][j], ai, bp[j]);
            }
        }
    }

    int jb = tx * 8;
#pragma unroll
    for (int i = 0; i < 4; i++) {
        int m = m0 + ty * 4 + i;
        if (m >= N_NODES) continue;
        float av[8];
#pragma unroll
        for (int j = 0; j < 4; j++) {
            float2 p = unpack2(acc[i][j]);
            av[2 * j] = p.x; av[2 * j + 1] = p.y;
        }
        if (jb < 64) {
            float o[8];
#pragma unroll
            for (int j = 0; j < 8; j++) o[j] = fast_tanh(av[j] + bias_s[jb + j]);
            float4* p = reinterpret_cast<float4*>(g_h1 + (size_t)m * 64 + jb);
            p[0] = make_float4(o[0], o[1], o[2], o[3]);
            p[1] = make_float4(o[4], o[5], o[6], o[7]);
        } else {
            float s = g_inv_out[m];
            union { __half2 h[4]; uint4 u; } pk;
#pragma unroll
            for (int p = 0; p < 4; p++) {
                float va = (av[2 * p]     + bias_s[jb + 2 * p])     * s;
                float vb = (av[2 * p + 1] + bias_s[jb + 2 * p + 1]) * s;
                pk.h[p] = __floats2half2_rn(va, vb);
            }
            *reinterpret_cast<uint4*>(g_xs + (size_t)m * 64 + (jb - 64)) = pk.u;
        }
    }
}

// ---------------- persistent warp-per-node CSR aggregation + fused ch-1 attention ----------------
__global__ __launch_bounds__(256) void k_agg(const float* __restrict__ att_w1,
                                             const float* __restrict__ att_b1,
                                             const float* __restrict__ att_w2) {
    __shared__ float W1s[64 * 32];
    __shared__ float b1s[32], w2s[32];
    __shared__ float red[8];

    int tid = threadIdx.x;
    for (int i = tid; i < 64 * 32; i += 256) W1s[i] = att_w1[i];
    if (tid < 32) { b1s[tid] = att_b1[tid]; w2s[tid] = att_w2[tid]; }
    __syncthreads();

    int warp = tid >> 5, lane = tid & 31;
    const __half2* xsh = reinterpret_cast<const __half2*>(g_xs);
    float part = 0.f;

    for (int n = blockIdx.x * 8 + warp; n < N_NODES; n += AGG_BLOCKS * 8) {
        int beg = g_rowstart[n];
        int deg = g_deg_in[n];
        int end = beg + deg;

        float2 acc = make_float2(0.f, 0.f);
        int e = beg;
        int end8 = beg + (deg & ~7);
        for (; e < end8; e += 8) {
            int s[8];
#pragma unroll
            for (int u = 0; u < 8; u++) s[u] = __ldg(&g_csr[e + u]);
            float2 f[8];
#pragma unroll
            for (int u = 0; u < 8; u++)
                f[u] = __half22float2(__ldg(&xsh[(size_t)s[u] * 32 + lane]));
            float ax = 0.f, ay = 0.f;
#pragma unroll
            for (int u = 0; u < 8; u++) { ax += f[u].x; ay += f[u].y; }
            acc.x += ax; acc.y += ay;
        }
        for (; e < end; e++) {
            int s0 = __ldg(&g_csr[e]);
            float2 f0 = __half22float2(__ldg(&xsh[(size_t)s0 * 32 + lane]));
            acc.x += f0.x; acc.y += f0.y;
        }
        float sc = rsqrtf(fmaxf((float)deg, 1.f));
        acc.x *= sc; acc.y *= sc;
        reinterpret_cast<float2*>(g_h2)[(size_t)n * 32 + lane] = acc;

        // ch-1 attention logit: lane j computes s_j = b1[j] + sum_k h2[k]*W1[k][j]
        float sj = b1s[lane];
#pragma unroll
        for (int k = 0; k < 32; k++) {
            float hx = __shfl_sync(0xffffffff, acc.x, k);
            float hy = __shfl_sync(0xffffffff, acc.y, k);
            sj = fmaf(hx, W1s[(2 * k) * 32 + lane], sj);
            sj = fmaf(hy, W1s[(2 * k + 1) * 32 + lane], sj);
        }
        part += fast_tanh(sj) * w2s[lane];
    }
#pragma unroll
    for (int off = 16; off > 0; off >>= 1)
        part += __shfl_down_sync(0xffffffff, part, off);
    if (lane == 0) red[warp] = part;
    __syncthreads();
    if (tid == 0) {
        float s = 0.f;
#pragma unroll
        for (int w = 0; w < 8; w++) s += red[w];
        atomicAdd(&g_wpart[1][blockIdx.x & 15], s);
    }
}

// ---------------- ch-0 attention logit sums (tiled over h1) ----------------
__global__ __launch_bounds__(128) void k_att(const float* __restrict__ att_w1,
                                             const float* __restrict__ att_b1,
                                             const float* __restrict__ att_w2) {
    __shared__ float Ws[64][32];
    __shared__ float As[8][128];
    __shared__ float b1s[32], w2s[32];
    __shared__ float redbuf[4];

    int tid = threadIdx.x;
    int m0  = blockIdx.x * 128;

    for (int i = tid; i < 64 * 32; i += 128) ((float*)Ws)[i] = att_w1[i];
    if (tid < 32) { b1s[tid] = att_b1[tid]; w2s[tid] = att_w2[tid]; }

    int tx = tid & 7, ty = tid >> 3;

    int m_load = m0 + tid;
    bool valid = m_load < N_NODES;
    const float4* hrow = reinterpret_cast<const float4*>(g_h1 + (size_t)m_load * 64);
    float4 z4 = make_float4(0.f, 0.f, 0.f, 0.f);

    float acc[8][4];
#pragma unroll
    for (int i = 0; i < 8; i++)
#pragma unroll
        for (int j = 0; j < 4; j++) acc[i][j] = 0.f;

    for (int kc = 0; kc < 64; kc += 8) {
        __syncthreads();
        float4 v0 = valid ? hrow[kc >> 2]       : z4;
        float4 v1 = valid ? hrow[(kc >> 2) + 1] : z4;
        As[0][tid] = v0.x; As[1][tid] = v0.y; As[2][tid] = v0.z; As[3][tid] = v0.w;
        As[4][tid] = v1.x; As[5][tid] = v1.y; As[6][tid] = v1.z; As[7][tid] = v1.w;
        __syncthreads();

#pragma unroll
        for (int k = 0; k < 8; k++) {
            float4 a0 = *reinterpret_cast<const float4*>(&As[k][ty * 8]);
            float4 a1 = *reinterpret_cast<const float4*>(&As[k][ty * 8 + 4]);
            float4 b  = *reinterpret_cast<const float4*>(&Ws[kc + k][tx * 4]);
            float a[8] = {a0.x, a0.y, a0.z, a0.w, a1.x, a1.y, a1.z, a1.w};
            float bb[4] = {b.x, b.y, b.z, b.w};
#pragma unroll
            for (int i = 0; i < 8; i++)
#pragma unroll
                for (int j = 0; j < 4; j++) acc[i][j] += a[i] * bb[j];
        }
    }

    float part = 0.f;
#pragma unroll
    for (int i = 0; i < 8; i++) {
        int m = m0 + ty * 8 + i;
        if (m >= N_NODES) continue;
#pragma unroll
        for (int j = 0; j < 4; j++)
            part += fast_tanh(acc[i][j] + b1s[tx * 4 + j]) * w2s[tx * 4 + j];
    }
#pragma unroll
    for (int off = 16; off > 0; off >>= 1)
        part += __shfl_down_sync(0xffffffff, part, off);
    if ((tid & 31) == 0) redbuf[tid >> 5] = part;
    __syncthreads();
    if (tid == 0)
        atomicAdd(&g_wpart[0][blockIdx.x & 15],
                  redbuf[0] + redbuf[1] + redbuf[2] + redbuf[3]);
}

// ---------------- final: beta softmax, blend, fc2 ----------------
__global__ __launch_bounds__(256) void k_out(const float* __restrict__ fc2_w,
                                             const float* __restrict__ fc2_b,
                                             float* __restrict__ out) {
    __shared__ float4 ws[16 * 16];
    __shared__ float bs[16];

    int tid = threadIdx.x;
    for (int i = tid; i < 16 * 16; i += 256)
        ws[i] = reinterpret_cast<const float4*>(fc2_w)[i];
    if (tid < 16) bs[tid] = fc2_b[tid];
    __syncthreads();

    int n = blockIdx.x * blockDim.x + tid;
    if (n >= N_NODES) return;

    float s0 = 0.f, s1 = 0.f;
#pragma unroll
    for (int i = 0; i < 16; i++) { s0 += g_wpart[0][i]; s1 += g_wpart[1][i]; }
    float m0 = s0 * (1.f / N_NODES);
    float m1 = s1 * (1.f / N_NODES);
    float mx = fmaxf(m0, m1);
    float e0 = expf(m0 - mx), e1 = expf(m1 - mx);
    float inv = 1.f / (e0 + e1);
    float b0 = e0 * inv, b1 = e1 * inv;

    const float4* r1 = reinterpret_cast<const float4*>(g_h1 + (size_t)n * 64);
    const float4* r2 = reinterpret_cast<const float4*>(g_h2 + (size_t)n * 64);
    float4 f[16];
#pragma unroll
    for (int i = 0; i < 16; i++) {
        float4 a = r1[i], b = r2[i];
        f[i] = make_float4(b0 * a.x + b1 * b.x, b0 * a.y + b1 * b.y,
                           b0 * a.z + b1 * b.z, b0 * a.w + b1 * b.w);
    }
    float o[16];
#pragma unroll
    for (int j = 0; j < 16; j++) {
        float acc = bs[j];
#pragma unroll
        for (int i = 0; i < 16; i++) {
            float4 w = ws[j * 16 + i];
            acc += f[i].x * w.x + f[i].y * w.y + f[i].z * w.z + f[i].w * w.w;
        }
        o[j] = acc;
    }
    float4* orow = reinterpret_cast<float4*>(out + (size_t)n * 16);
#pragma unroll
    for (int j = 0; j < 4; j++)
        orow[j] = make_float4(o[j * 4], o[j * 4 + 1], o[j * 4 + 2], o[j * 4 + 3]);
}

// ---------------- launch: fork-join two-stream graph ----------------
extern "C" void kernel_launch(void* const* d_in, const int* in_sizes, int n_in,
                              void* d_out, int out_size)
{
    const float* feat   = (const float*)d_in[0];
    const int*   e_src  = (const int*)  d_in[1];
    const int*   e_dst  = (const int*)  d_in[2];
    const float* fc1_w  = (const float*)d_in[3];
    const float* fc1_b  = (const float*)d_in[4];
    const float* filt_w = (const float*)d_in[5];
    const float* filt_b = (const float*)d_in[6];
    const float* att_w1 = (const float*)d_in[7];
    const float* att_b1 = (const float*)d_in[8];
    const float* att_w2 = (const float*)d_in[9];
    const float* fc2_w  = (const float*)d_in[10];
    const float* fc2_b  = (const float*)d_in[11];
    float* out = (float*)d_out;

    static cudaStream_t s1 = nullptr;
    static cudaEvent_t ev_deg = nullptr, ev_gemm = nullptr, ev_att = nullptr;
    if (!s1) {
        cudaStreamCreateWithFlags(&s1, cudaStreamNonBlocking);
        cudaEventCreateWithFlags(&ev_deg,  cudaEventDisableTiming);
        cudaEventCreateWithFlags(&ev_gemm, cudaEventDisableTiming);
        cudaEventCreateWithFlags(&ev_att,  cudaEventDisableTiming);
    }
    cudaStream_t s0 = (cudaStream_t)0;

    // main chain: degrees -> scan -> CSR
    k_init<<<(N_NODES + 255) / 256, 256, 0, s0>>>();
    k_degree<<<(N_EDGES / 4 + 255) / 256, 256, 0, s0>>>((const int4*)e_src, (const int4*)e_dst);
    cudaEventRecord(ev_deg, s0);

    // side chain: prep -> dual GEMM -> ch-0 attention
    cudaStreamWaitEvent(s1, ev_deg, 0);
    k_prep<<<(N_NODES + 255) / 256, 256, 0, s1>>>(fc1_w, fc1_b, filt_w, filt_b);
    k_gemm<<<(N_NODES + 127) / 128, 512, 0, s1>>>(feat);
    cudaEventRecord(ev_gemm, s1);
    k_att<<<(N_NODES + 127) / 128, 128, 0, s1>>>(att_w1, att_b1, att_w2);
    cudaEventRecord(ev_att, s1);

    // main chain continues in parallel
    k_scan1<<<NB_SCAN, 256, 0, s0>>>();
    k_scan2<<<1, 512, 0, s0>>>();
    k_scan3<<<(N_NODES + 255) / 256, 256, 0, s0>>>();
    k_csr<<<(N_EDGES + 255) / 256, 256, 0, s0>>>(e_src, e_dst);

    // join: aggregation needs CSR (s0) + xs (gemm, s1)
    cudaStreamWaitEvent(s0, ev_gemm, 0);
    k_agg<<<AGG_BLOCKS, 256, 0, s0>>>(att_w1, att_b1, att_w2);

    // join: output needs ch-0 logits (s1) + everything on s0
    cudaStreamWaitEvent(s0, ev_att, 0);
    k_out<<<(N_NODES + 255) / 256, 256, 0, s0>>>(fc2_w, fc2_b, out);
}

// round 7
// speedup vs baseline: 1.1922x; 1.1922x over previous
#include <cuda_runtime.h>
#include <cuda_fp16.h>
#include <math.h>

#define N_NODES 100000
#define N_EDGES 1600000
#define NB_SCAN 391   // ceil(100000/256)

// ---------------- scratch (device globals) ----------------
__device__ float  g_h1[(size_t)N_NODES * 64];   // tanh MLP branch (fp32)
__device__ __half g_xs[(size_t)N_NODES * 64];   // filter linear out * inv_out (fp16)
__device__ float  g_h2[(size_t)N_NODES * 64];   // aggregated branch (inv_in applied)
__device__ int    g_deg_out[N_NODES];
__device__ int    g_deg_in [N_NODES];
__device__ float  g_inv_out[N_NODES];
__device__ int    g_rowstart[N_NODES];
__device__ int    g_cursor[N_NODES];
__device__ int    g_part[512];
__device__ int    g_csr[N_EDGES];
__device__ float  g_W[64 * 128];                // fused [k][j]: j<64 fc1, j>=64 filt
__device__ float  g_bias[128];
__device__ float  g_wpart[2][16];               // attention logit partial sums

__device__ __forceinline__ float fast_tanh(float x) {
    float e = __expf(2.f * x);
    return 1.f - __fdividef(2.f, e + 1.f);
}

// ---- packed f32x2 helpers (sm_103a) ----
__device__ __forceinline__ unsigned long long pack2(float lo, float hi) {
    unsigned long long r;
    asm("mov.b64 %0, {%1, %2};" : "=l"(r) : "f"(lo), "f"(hi));
    return r;
}
__device__ __forceinline__ float2 unpack2(unsigned long long v) {
    float2 r;
    asm("mov.b64 {%0, %1}, %2;" : "=f"(r.x), "=f"(r.y) : "l"(v));
    return r;
}
__device__ __forceinline__ void fma2(unsigned long long& d, unsigned long long a,
                                     unsigned long long b) {
    asm("fma.rn.f32x2 %0, %1, %2, %0;" : "+l"(d) : "l"(a), "l"(b));
}

// ---------------- zero scratch ----------------
__global__ void k_init() {
    int i = blockIdx.x * blockDim.x + threadIdx.x;
    if (i < N_NODES) { g_deg_out[i] = 0; g_deg_in[i] = 0; }
    if (i < 32) g_wpart[i >> 4][i & 15] = 0.f;
}

// ---------------- degree histogram (4 edges / thread) ----------------
__global__ void k_degree(const int4* __restrict__ src4, const int4* __restrict__ dst4) {
    int i = blockIdx.x * blockDim.x + threadIdx.x;
    if (i >= N_EDGES / 4) return;
    int4 s = __ldg(&src4[i]);
    int4 d = __ldg(&dst4[i]);
    atomicAdd(&g_deg_out[s.x], 1); atomicAdd(&g_deg_out[s.y], 1);
    atomicAdd(&g_deg_out[s.z], 1); atomicAdd(&g_deg_out[s.w], 1);
    atomicAdd(&g_deg_in[d.x], 1);  atomicAdd(&g_deg_in[d.y], 1);
    atomicAdd(&g_deg_in[d.z], 1);  atomicAdd(&g_deg_in[d.w], 1);
}

// ---------------- inv_out + fused weight prep (side stream) ----------------
__global__ void k_prep(const float* __restrict__ fc1_w, const float* __restrict__ fc1_b,
                       const float* __restrict__ filt_w, const float* __restrict__ filt_b) {
    int i = blockIdx.x * blockDim.x + threadIdx.x;
    if (i < N_NODES) g_inv_out[i] = rsqrtf(fmaxf((float)g_deg_out[i], 1.f));
    if (i < 64 * 128) {
        int k = i >> 7, j = i & 127;
        g_W[i] = (j < 64) ? fc1_w[j * 64 + k] : filt_w[(j - 64) * 64 + k];
    }
    if (i < 128) g_bias[i] = (i < 64) ? fc1_b[i] : filt_b[i - 64];
}

// ---------------- exclusive scan of deg_in (3 stages) ----------------
__global__ void k_scan1() {
    __shared__ int sh[256];
    int t = threadIdx.x;
    int i = blockIdx.x * 256 + t;
    int v = (i < N_NODES) ? g_deg_in[i] : 0;
    sh[t] = v;
    __syncthreads();
#pragma unroll
    for (int off = 1; off < 256; off <<= 1) {
        int add = (t >= off) ? sh[t - off] : 0;
        __syncthreads();
        sh[t] += add;
        __syncthreads();
    }
    if (i < N_NODES) g_rowstart[i] = sh[t] - v;
    if (t == 255) g_part[blockIdx.x] = sh[255];
}

__global__ void k_scan2() {
    __shared__ int sh[512];
    int t = threadIdx.x;
    int v = (t < NB_SCAN) ? g_part[t] : 0;
    sh[t] = v;
    __syncthreads();
#pragma unroll
    for (int off = 1; off < 512; off <<= 1) {
        int add = (t >= off) ? sh[t - off] : 0;
        __syncthreads();
        sh[t] += add;
        __syncthreads();
    }
    if (t < NB_SCAN) g_part[t] = sh[t] - v;
}

__global__ void k_scan3() {
    int i = blockIdx.x * blockDim.x + threadIdx.x;
    if (i < N_NODES) {
        int rs = g_rowstart[i] + g_part[i >> 8];
        g_rowstart[i] = rs;
        g_cursor[i]   = rs;
    }
}

// ---------------- CSR build (counting sort by dst) ----------------
__global__ void k_csr(const int* __restrict__ src, const int* __restrict__ dst) {
    int e = blockIdx.x * blockDim.x + threadIdx.x;
    if (e >= N_EDGES) return;
    int d = __ldg(&dst[e]);
    int pos = atomicAdd(&g_cursor[d], 1);
    g_csr[pos] = __ldg(&src[e]);
}

// ---------------- tiled dual GEMM: 128 thr, 8x16 f32x2 thread tile ----------------
// Bs bank-padded: row stride 160 words, 16-float chunks at stride 20 words
// (tx*20 mod 32 = {0,20,8,28,16,4,24,12} -> conflict-free LDS.128 across tx)
__global__ __launch_bounds__(128) void k_gemm(const float* __restrict__ feat) {
    __shared__ float Bs[64 * 160];   // 40KB
    __shared__ float As[8][128];     // 4KB
    __shared__ float bias_s[128];

    int tid = threadIdx.x;
    int m0 = blockIdx.x * 128;

    const float4* w4 = reinterpret_cast<const float4*>(g_W);
    for (int i4 = tid; i4 < 2048; i4 += 128) {
        int row = i4 >> 5, c4 = i4 & 31;
        int chunk = c4 >> 2, off = (c4 & 3) * 4;
        *reinterpret_cast<float4*>(&Bs[row * 160 + chunk * 20 + off]) = w4[i4];
    }
    bias_s[tid] = g_bias[tid];

    int tx = tid & 7, ty = tid >> 3;   // tx: 8 col-groups of 16, ty: 16 node-groups of 8

    unsigned long long acc[8][8];      // 8 nodes x 8 f32x2 pairs (16 cols)
#pragma unroll
    for (int i = 0; i < 8; i++)
#pragma unroll
        for (int j = 0; j < 8; j++) acc[i][j] = 0ull;

    int m_load = m0 + tid;
    bool valid = m_load < N_NODES;
    const float4* frow = reinterpret_cast<const float4*>(feat + (size_t)m_load * 64);
    float4 z4 = make_float4(0.f, 0.f, 0.f, 0.f);

    for (int kc = 0; kc < 64; kc += 8) {
        __syncthreads();
        float4 v0 = valid ? frow[kc >> 2]       : z4;
        float4 v1 = valid ? frow[(kc >> 2) + 1] : z4;
        As[0][tid] = v0.x; As[1][tid] = v0.y; As[2][tid] = v0.z; As[3][tid] = v0.w;
        As[4][tid] = v1.x; As[5][tid] = v1.y; As[6][tid] = v1.z; As[7][tid] = v1.w;
        __syncthreads();

#pragma unroll
        for (int k = 0; k < 8; k++) {
            float4 a0 = *reinterpret_cast<const float4*>(&As[k][ty * 8]);
            float4 a1 = *reinterpret_cast<const float4*>(&As[k][ty * 8 + 4]);
            const float* brow = &Bs[(kc + k) * 160 + tx * 20];
            ulonglong2 p0 = *reinterpret_cast<const ulonglong2*>(brow);
            ulonglong2 p1 = *reinterpret_cast<const ulonglong2*>(brow + 4);
            ulonglong2 p2 = *reinterpret_cast<const ulonglong2*>(brow + 8);
            ulonglong2 p3 = *reinterpret_cast<const ulonglong2*>(brow + 12);
            unsigned long long bp[8] = {p0.x, p0.y, p1.x, p1.y, p2.x, p2.y, p3.x, p3.y};
            float a[8] = {a0.x, a0.y, a0.z, a0.w, a1.x, a1.y, a1.z, a1.w};
#pragma unroll
            for (int i = 0; i < 8; i++) {
                unsigned long long ai = pack2(a[i], a[i]);
#pragma unroll
                for (int j = 0; j < 8; j++) fma2(acc[i][j], ai, bp[j]);
            }
        }
    }

    int jb = tx * 16;
#pragma unroll
    for (int i = 0; i < 8; i++) {
        int m = m0 + ty * 8 + i;
        if (m >= N_NODES) continue;
        float av[16];
#pragma unroll
        for (int j = 0; j < 8; j++) {
            float2 p = unpack2(acc[i][j]);
            av[2 * j] = p.x; av[2 * j + 1] = p.y;
        }
        if (jb < 64) {
            float o[16];
#pragma unroll
            for (int j = 0; j < 16; j++) o[j] = fast_tanh(av[j] + bias_s[jb + j]);
            float4* p = reinterpret_cast<float4*>(g_h1 + (size_t)m * 64 + jb);
            p[0] = make_float4(o[0],  o[1],  o[2],  o[3]);
            p[1] = make_float4(o[4],  o[5],  o[6],  o[7]);
            p[2] = make_float4(o[8],  o[9],  o[10], o[11]);
            p[3] = make_float4(o[12], o[13], o[14], o[15]);
        } else {
            float s = g_inv_out[m];
            union { __half2 h[8]; uint4 u[2]; } pk;
#pragma unroll
            for (int p = 0; p < 8; p++) {
                float va = (av[2 * p]     + bias_s[jb + 2 * p])     * s;
                float vb = (av[2 * p + 1] + bias_s[jb + 2 * p + 1]) * s;
                pk.h[p] = __floats2half2_rn(va, vb);
            }
            uint4* dst = reinterpret_cast<uint4*>(g_xs + (size_t)m * 64 + (jb - 64));
            dst[0] = pk.u[0];
            dst[1] = pk.u[1];
        }
    }
}

// ---------------- warp-per-node CSR aggregation + fused ch-1 attention ----------------
__global__ __launch_bounds__(256) void k_agg(const float* __restrict__ att_w1,
                                             const float* __restrict__ att_b1,
                                             const float* __restrict__ att_w2) {
    __shared__ float W1s[64 * 32];
    __shared__ float b1s[32], w2s[32];
    __shared__ float red[8];

    int tid = threadIdx.x;
    for (int i = tid; i < 64 * 32; i += 256) W1s[i] = att_w1[i];
    if (tid < 32) { b1s[tid] = att_b1[tid]; w2s[tid] = att_w2[tid]; }
    __syncthreads();

    int warp = tid >> 5, lane = tid & 31;
    int n = blockIdx.x * 8 + warp;
    float part = 0.f;

    if (n < N_NODES) {
        int beg = g_rowstart[n];
        int deg = g_deg_in[n];
        int end = beg + deg;

        float2 acc = make_float2(0.f, 0.f);
        const __half2* xsh = reinterpret_cast<const __half2*>(g_xs);
        int e = beg;
        int end8 = beg + (deg & ~7);
        for (; e < end8; e += 8) {
            int s[8];
#pragma unroll
            for (int u = 0; u < 8; u++) s[u] = __ldg(&g_csr[e + u]);
            float2 f[8];
#pragma unroll
            for (int u = 0; u < 8; u++)
                f[u] = __half22float2(__ldg(&xsh[(size_t)s[u] * 32 + lane]));
            float ax = 0.f, ay = 0.f;
#pragma unroll
            for (int u = 0; u < 8; u++) { ax += f[u].x; ay += f[u].y; }
            acc.x += ax; acc.y += ay;
        }
        for (; e < end; e++) {
            int s0 = __ldg(&g_csr[e]);
            float2 f0 = __half22float2(__ldg(&xsh[(size_t)s0 * 32 + lane]));
            acc.x += f0.x; acc.y += f0.y;
        }
        float sc = rsqrtf(fmaxf((float)deg, 1.f));
        acc.x *= sc; acc.y *= sc;
        reinterpret_cast<float2*>(g_h2)[(size_t)n * 32 + lane] = acc;

        // ch-1 attention logit: lane j computes s_j = b1[j] + sum_k h2[k]*W1[k][j]
        float sj = b1s[lane];
#pragma unroll
        for (int k = 0; k < 32; k++) {
            float hx = __shfl_sync(0xffffffff, acc.x, k);
            float hy = __shfl_sync(0xffffffff, acc.y, k);
            sj = fmaf(hx, W1s[(2 * k) * 32 + lane], sj);
            sj = fmaf(hy, W1s[(2 * k + 1) * 32 + lane], sj);
        }
        part = fast_tanh(sj) * w2s[lane];
    }
#pragma unroll
    for (int off = 16; off > 0; off >>= 1)
        part += __shfl_down_sync(0xffffffff, part, off);
    if (lane == 0) red[warp] = part;
    __syncthreads();
    if (tid == 0) {
        float s = 0.f;
#pragma unroll
        for (int w = 0; w < 8; w++) s += red[w];
        atomicAdd(&g_wpart[1][blockIdx.x & 15], s);
    }
}

// ---------------- ch-0 attention logit sums (tiled over h1) ----------------
__global__ __launch_bounds__(128) void k_att(const float* __restrict__ att_w1,
                                             const float* __restrict__ att_b1,
                                             const float* __restrict__ att_w2) {
    __shared__ float Ws[64][32];
    __shared__ float As[8][128];
    __shared__ float b1s[32], w2s[32];
    __shared__ float redbuf[4];

    int tid = threadIdx.x;
    int m0  = blockIdx.x * 128;

    for (int i = tid; i < 64 * 32; i += 128) ((float*)Ws)[i] = att_w1[i];
    if (tid < 32) { b1s[tid] = att_b1[tid]; w2s[tid] = att_w2[tid]; }

    int tx = tid & 7, ty = tid >> 3;

    int m_load = m0 + tid;
    bool valid = m_load < N_NODES;
    const float4* hrow = reinterpret_cast<const float4*>(g_h1 + (size_t)m_load * 64);
    float4 z4 = make_float4(0.f, 0.f, 0.f, 0.f);

    float acc[8][4];
#pragma unroll
    for (int i = 0; i < 8; i++)
#pragma unroll
        for (int j = 0; j < 4; j++) acc[i][j] = 0.f;

    for (int kc = 0; kc < 64; kc += 8) {
        __syncthreads();
        float4 v0 = valid ? hrow[kc >> 2]       : z4;
        float4 v1 = valid ? hrow[(kc >> 2) + 1] : z4;
        As[0][tid] = v0.x; As[1][tid] = v0.y; As[2][tid] = v0.z; As[3][tid] = v0.w;
        As[4][tid] = v1.x; As[5][tid] = v1.y; As[6][tid] = v1.z; As[7][tid] = v1.w;
        __syncthreads();

#pragma unroll
        for (int k = 0; k < 8; k++) {
            float4 a0 = *reinterpret_cast<const float4*>(&As[k][ty * 8]);
            float4 a1 = *reinterpret_cast<const float4*>(&As[k][ty * 8 + 4]);
            float4 b  = *reinterpret_cast<const float4*>(&Ws[kc + k][tx * 4]);
            float a[8] = {a0.x, a0.y, a0.z, a0.w, a1.x, a1.y, a1.z, a1.w};
            float bb[4] = {b.x, b.y, b.z, b.w};
#pragma unroll
            for (int i = 0; i < 8; i++)
#pragma unroll
                for (int j = 0; j < 4; j++) acc[i][j] += a[i] * bb[j];
        }
    }

    float part = 0.f;
#pragma unroll
    for (int i = 0; i < 8; i++) {
        int m = m0 + ty * 8 + i;
        if (m >= N_NODES) continue;
#pragma unroll
        for (int j = 0; j < 4; j++)
            part += fast_tanh(acc[i][j] + b1s[tx * 4 + j]) * w2s[tx * 4 + j];
    }
#pragma unroll
    for (int off = 16; off > 0; off >>= 1)
        part += __shfl_down_sync(0xffffffff, part, off);
    if ((tid & 31) == 0) redbuf[tid >> 5] = part;
    __syncthreads();
    if (tid == 0)
        atomicAdd(&g_wpart[0][blockIdx.x & 15],
                  redbuf[0] + redbuf[1] + redbuf[2] + redbuf[3]);
}

// ---------------- final: beta softmax, blend, fc2 ----------------
__global__ __launch_bounds__(256) void k_out(const float* __restrict__ fc2_w,
                                             const float* __restrict__ fc2_b,
                                             float* __restrict__ out) {
    __shared__ float4 ws[16 * 16];
    __shared__ float bs[16];

    int tid = threadIdx.x;
    for (int i = tid; i < 16 * 16; i += 256)
        ws[i] = reinterpret_cast<const float4*>(fc2_w)[i];
    if (tid < 16) bs[tid] = fc2_b[tid];
    __syncthreads();

    int n = blockIdx.x * blockDim.x + tid;
    if (n >= N_NODES) return;

    float s0 = 0.f, s1 = 0.f;
#pragma unroll
    for (int i = 0; i < 16; i++) { s0 += g_wpart[0][i]; s1 += g_wpart[1][i]; }
    float m0 = s0 * (1.f / N_NODES);
    float m1 = s1 * (1.f / N_NODES);
    float mx = fmaxf(m0, m1);
    float e0 = expf(m0 - mx), e1 = expf(m1 - mx);
    float inv = 1.f / (e0 + e1);
    float b0 = e0 * inv, b1 = e1 * inv;

    const float4* r1 = reinterpret_cast<const float4*>(g_h1 + (size_t)n * 64);
    const float4* r2 = reinterpret_cast<const float4*>(g_h2 + (size_t)n * 64);
    float4 f[16];
#pragma unroll
    for (int i = 0; i < 16; i++) {
        float4 a = r1[i], b = r2[i];
        f[i] = make_float4(b0 * a.x + b1 * b.x, b0 * a.y + b1 * b.y,
                           b0 * a.z + b1 * b.z, b0 * a.w + b1 * b.w);
    }
    float o[16];
#pragma unroll
    for (int j = 0; j < 16; j++) {
        float acc = bs[j];
#pragma unroll
        for (int i = 0; i < 16; i++) {
            float4 w = ws[j * 16 + i];
            acc += f[i].x * w.x + f[i].y * w.y + f[i].z * w.z + f[i].w * w.w;
        }
        o[j] = acc;
    }
    float4* orow = reinterpret_cast<float4*>(out + (size_t)n * 16);
#pragma unroll
    for (int j = 0; j < 4; j++)
        orow[j] = make_float4(o[j * 4], o[j * 4 + 1], o[j * 4 + 2], o[j * 4 + 3]);
}

// ---------------- launch: fork-join two-stream graph ----------------
extern "C" void kernel_launch(void* const* d_in, const int* in_sizes, int n_in,
                              void* d_out, int out_size)
{
    const float* feat   = (const float*)d_in[0];
    const int*   e_src  = (const int*)  d_in[1];
    const int*   e_dst  = (const int*)  d_in[2];
    const float* fc1_w  = (const float*)d_in[3];
    const float* fc1_b  = (const float*)d_in[4];
    const float* filt_w = (const float*)d_in[5];
    const float* filt_b = (const float*)d_in[6];
    const float* att_w1 = (const float*)d_in[7];
    const float* att_b1 = (const float*)d_in[8];
    const float* att_w2 = (const float*)d_in[9];
    const float* fc2_w  = (const float*)d_in[10];
    const float* fc2_b  = (const float*)d_in[11];
    float* out = (float*)d_out;

    static cudaStream_t s1 = nullptr;
    static cudaEvent_t ev_deg = nullptr, ev_gemm = nullptr, ev_att = nullptr;
    if (!s1) {
        cudaStreamCreateWithFlags(&s1, cudaStreamNonBlocking);
        cudaEventCreateWithFlags(&ev_deg,  cudaEventDisableTiming);
        cudaEventCreateWithFlags(&ev_gemm, cudaEventDisableTiming);
        cudaEventCreateWithFlags(&ev_att,  cudaEventDisableTiming);
    }
    cudaStream_t s0 = (cudaStream_t)0;

    // main chain: degrees -> scan -> CSR
    k_init<<<(N_NODES + 255) / 256, 256, 0, s0>>>();
    k_degree<<<(N_EDGES / 4 + 255) / 256, 256, 0, s0>>>((const int4*)e_src, (const int4*)e_dst);
    cudaEventRecord(ev_deg, s0);

    // side chain: prep -> dual GEMM -> ch-0 attention
    cudaStreamWaitEvent(s1, ev_deg, 0);
    k_prep<<<(N_NODES + 255) / 256, 256, 0, s1>>>(fc1_w, fc1_b, filt_w, filt_b);
    k_gemm<<<(N_NODES + 127) / 128, 128, 0, s1>>>(feat);
    cudaEventRecord(ev_gemm, s1);
    k_att<<<(N_NODES + 127) / 128, 128, 0, s1>>>(att_w1, att_b1, att_w2);
    cudaEventRecord(ev_att, s1);

    // main chain continues in parallel
    k_scan1<<<NB_SCAN, 256, 0, s0>>>();
    k_scan2<<<1, 512, 0, s0>>>();
    k_scan3<<<(N_NODES + 255) / 256, 256, 0, s0>>>();
    k_csr<<<(N_EDGES + 255) / 256, 256, 0, s0>>>(e_src, e_dst);

    // join: aggregation needs CSR (s0) + xs (gemm, s1)
    cudaStreamWaitEvent(s0, ev_gemm, 0);
    k_agg<<<(N_NODES + 7) / 8, 256, 0, s0>>>(att_w1, att_b1, att_w2);

    // join: output needs ch-0 logits (s1) + everything on s0
    cudaStreamWaitEvent(s0, ev_att, 0);
    k_out<<<(N_NODES + 255) / 256, 256, 0, s0>>>(fc2_w, fc2_b, out);
}

// round 8
// speedup vs baseline: 1.3793x; 1.1569x over previous
#include <cuda_runtime.h>
#include <cuda_fp16.h>
#include <math.h>

#define N_NODES 100000
#define N_EDGES 1600000
#define NB_SCAN 391   // ceil(100000/256)

// ---------------- scratch (device globals) ----------------
__device__ float  g_h1[(size_t)N_NODES * 64];   // tanh MLP branch (fp32)
__device__ __half g_xs[(size_t)N_NODES * 64];   // filter linear out * inv_out (fp16)
__device__ float  g_h2[(size_t)N_NODES * 64];   // aggregated branch (inv_in applied)
__device__ int    g_deg_out[N_NODES];
__device__ int    g_deg_in [N_NODES];
__device__ float  g_inv_out[N_NODES];
__device__ int    g_rowstart[N_NODES];
__device__ int    g_cursor[N_NODES];
__device__ int    g_part[512];
__device__ int    g_csr[N_EDGES];
__device__ float  g_W[64 * 128];                // fused [k][j]: j<64 fc1, j>=64 filt
__device__ float  g_bias[128];
__device__ float  g_wpart[2][16];               // attention logit partial sums

__device__ __forceinline__ float fast_tanh(float x) {
    float e = __expf(2.f * x);
    return 1.f - __fdividef(2.f, e + 1.f);
}

// ---- packed f32x2 helpers (sm_103a) ----
__device__ __forceinline__ unsigned long long pack2(float lo, float hi) {
    unsigned long long r;
    asm("mov.b64 %0, {%1, %2};" : "=l"(r) : "f"(lo), "f"(hi));
    return r;
}
__device__ __forceinline__ float2 unpack2(unsigned long long v) {
    float2 r;
    asm("mov.b64 {%0, %1}, %2;" : "=f"(r.x), "=f"(r.y) : "l"(v));
    return r;
}
__device__ __forceinline__ void fma2(unsigned long long& d, unsigned long long a,
                                     unsigned long long b) {
    asm("fma.rn.f32x2 %0, %1, %2, %0;" : "+l"(d) : "l"(a), "l"(b));
}

// ---------------- zero scratch ----------------
__global__ void k_init() {
    int i = blockIdx.x * blockDim.x + threadIdx.x;
    if (i < N_NODES) { g_deg_out[i] = 0; g_deg_in[i] = 0; }
    if (i < 32) g_wpart[i >> 4][i & 15] = 0.f;
}

// ---------------- degree histogram (4 edges / thread) ----------------
__global__ void k_degree(const int4* __restrict__ src4, const int4* __restrict__ dst4) {
    int i = blockIdx.x * blockDim.x + threadIdx.x;
    if (i >= N_EDGES / 4) return;
    int4 s = __ldg(&src4[i]);
    int4 d = __ldg(&dst4[i]);
    atomicAdd(&g_deg_out[s.x], 1); atomicAdd(&g_deg_out[s.y], 1);
    atomicAdd(&g_deg_out[s.z], 1); atomicAdd(&g_deg_out[s.w], 1);
    atomicAdd(&g_deg_in[d.x], 1);  atomicAdd(&g_deg_in[d.y], 1);
    atomicAdd(&g_deg_in[d.z], 1);  atomicAdd(&g_deg_in[d.w], 1);
}

// ---------------- inv_out + fused weight prep (side stream) ----------------
__global__ void k_prep(const float* __restrict__ fc1_w, const float* __restrict__ fc1_b,
                       const float* __restrict__ filt_w, const float* __restrict__ filt_b) {
    int i = blockIdx.x * blockDim.x + threadIdx.x;
    if (i < N_NODES) g_inv_out[i] = rsqrtf(fmaxf((float)g_deg_out[i], 1.f));
    if (i < 64 * 128) {
        int k = i >> 7, j = i & 127;
        g_W[i] = (j < 64) ? fc1_w[j * 64 + k] : filt_w[(j - 64) * 64 + k];
    }
    if (i < 128) g_bias[i] = (i < 64) ? fc1_b[i] : filt_b[i - 64];
}

// ---------------- exclusive scan of deg_in (3 stages) ----------------
__global__ void k_scan1() {
    __shared__ int sh[256];
    int t = threadIdx.x;
    int i = blockIdx.x * 256 + t;
    int v = (i < N_NODES) ? g_deg_in[i] : 0;
    sh[t] = v;
    __syncthreads();
#pragma unroll
    for (int off = 1; off < 256; off <<= 1) {
        int add = (t >= off) ? sh[t - off] : 0;
        __syncthreads();
        sh[t] += add;
        __syncthreads();
    }
    if (i < N_NODES) g_rowstart[i] = sh[t] - v;
    if (t == 255) g_part[blockIdx.x] = sh[255];
}

__global__ void k_scan2() {
    __shared__ int sh[512];
    int t = threadIdx.x;
    int v = (t < NB_SCAN) ? g_part[t] : 0;
    sh[t] = v;
    __syncthreads();
#pragma unroll
    for (int off = 1; off < 512; off <<= 1) {
        int add = (t >= off) ? sh[t - off] : 0;
        __syncthreads();
        sh[t] += add;
        __syncthreads();
    }
    if (t < NB_SCAN) g_part[t] = sh[t] - v;
}

__global__ void k_scan3() {
    int i = blockIdx.x * blockDim.x + threadIdx.x;
    if (i < N_NODES) {
        int rs = g_rowstart[i] + g_part[i >> 8];
        g_rowstart[i] = rs;
        g_cursor[i]   = rs;
    }
}

// ---------------- CSR build (counting sort by dst) ----------------
__global__ void k_csr(const int* __restrict__ src, const int* __restrict__ dst) {
    int e = blockIdx.x * blockDim.x + threadIdx.x;
    if (e >= N_EDGES) return;
    int d = __ldg(&dst[e]);
    int pos = atomicAdd(&g_cursor[d], 1);
    g_csr[pos] = __ldg(&src[e]);
}

// ---------------- tiled dual GEMM (R5 config): 256 thr, 8x8 f32x2 tile ----------------
__global__ __launch_bounds__(256) void k_gemm(const float* __restrict__ feat) {
    __shared__ float Bs[64][128];
    __shared__ float As[16][128];
    __shared__ float bias_s[128];

    int tid = threadIdx.x;
    int m0 = blockIdx.x * 128;

    for (int i = tid; i < 64 * 128; i += 256) ((float*)Bs)[i] = g_W[i];
    if (tid < 128) bias_s[tid] = g_bias[tid];

    int tx = tid & 15, ty = tid >> 4;
    int r  = tid & 127, hf = tid >> 7;

    unsigned long long acc[8][4];
#pragma unroll
    for (int i = 0; i < 8; i++)
#pragma unroll
        for (int j = 0; j < 4; j++) acc[i][j] = 0ull;

    int m_load = m0 + r;
    bool valid = m_load < N_NODES;
    const float4* frow = reinterpret_cast<const float4*>(feat + (size_t)m_load * 64);
    float4 z4 = make_float4(0.f, 0.f, 0.f, 0.f);

    for (int kc = 0; kc < 64; kc += 16) {
        __syncthreads();
        float4 v0 = valid ? frow[(kc >> 2) + hf * 2]     : z4;
        float4 v1 = valid ? frow[(kc >> 2) + hf * 2 + 1] : z4;
        int kb = hf * 8;
        As[kb + 0][r] = v0.x; As[kb + 1][r] = v0.y; As[kb + 2][r] = v0.z; As[kb + 3][r] = v0.w;
        As[kb + 4][r] = v1.x; As[kb + 5][r] = v1.y; As[kb + 6][r] = v1.z; As[kb + 7][r] = v1.w;
        __syncthreads();

#pragma unroll
        for (int k = 0; k < 16; k++) {
            float4 a0 = *reinterpret_cast<const float4*>(&As[k][ty * 8]);
            float4 a1 = *reinterpret_cast<const float4*>(&As[k][ty * 8 + 4]);
            ulonglong2 b01 = *reinterpret_cast<const ulonglong2*>(&Bs[kc + k][tx * 8]);
            ulonglong2 b23 = *reinterpret_cast<const ulonglong2*>(&Bs[kc + k][tx * 8 + 4]);
            float a[8] = {a0.x, a0.y, a0.z, a0.w, a1.x, a1.y, a1.z, a1.w};
            unsigned long long bp[4] = {b01.x, b01.y, b23.x, b23.y};
#pragma unroll
            for (int i = 0; i < 8; i++) {
                unsigned long long ai = pack2(a[i], a[i]);
#pragma unroll
                for (int j = 0; j < 4; j++) fma2(acc[i][j], ai, bp[j]);
            }
        }
    }

    int jb = tx * 8;
#pragma unroll
    for (int i = 0; i < 8; i++) {
        int m = m0 + ty * 8 + i;
        if (m >= N_NODES) continue;
        float av[8];
#pragma unroll
        for (int j = 0; j < 4; j++) {
            float2 p = unpack2(acc[i][j]);
            av[2 * j] = p.x; av[2 * j + 1] = p.y;
        }
        if (jb < 64) {
            float o[8];
#pragma unroll
            for (int j = 0; j < 8; j++) o[j] = fast_tanh(av[j] + bias_s[jb + j]);
            float4* p = reinterpret_cast<float4*>(g_h1 + (size_t)m * 64 + jb);
            p[0] = make_float4(o[0], o[1], o[2], o[3]);
            p[1] = make_float4(o[4], o[5], o[6], o[7]);
        } else {
            float s = g_inv_out[m];
            union { __half2 h[4]; uint4 u; } pk;
#pragma unroll
            for (int p = 0; p < 4; p++) {
                float va = (av[2 * p]     + bias_s[jb + 2 * p])     * s;
                float vb = (av[2 * p + 1] + bias_s[jb + 2 * p + 1]) * s;
                pk.h[p] = __floats2half2_rn(va, vb);
            }
            *reinterpret_cast<uint4*>(g_xs + (size_t)m * 64 + (jb - 64)) = pk.u;
        }
    }
}

// ---------------- warp-per-node CSR aggregation (pure gather, no attention) ----------------
__global__ __launch_bounds__(256) void k_agg() {
    int tid = threadIdx.x;
    int warp = tid >> 5, lane = tid & 31;
    int n = blockIdx.x * 8 + warp;
    if (n >= N_NODES) return;

    int beg = g_rowstart[n];
    int deg = g_deg_in[n];
    int end = beg + deg;

    float2 acc = make_float2(0.f, 0.f);
    const __half2* xsh = reinterpret_cast<const __half2*>(g_xs);
    int e = beg;
    int end8 = beg + (deg & ~7);
    for (; e < end8; e += 8) {
        int s[8];
#pragma unroll
        for (int u = 0; u < 8; u++) s[u] = __ldg(&g_csr[e + u]);
        float2 f[8];
#pragma unroll
        for (int u = 0; u < 8; u++)
            f[u] = __half22float2(__ldg(&xsh[(size_t)s[u] * 32 + lane]));
        float ax = 0.f, ay = 0.f;
#pragma unroll
        for (int u = 0; u < 8; u++) { ax += f[u].x; ay += f[u].y; }
        acc.x += ax; acc.y += ay;
    }
    for (; e < end; e++) {
        int s0 = __ldg(&g_csr[e]);
        float2 f0 = __half22float2(__ldg(&xsh[(size_t)s0 * 32 + lane]));
        acc.x += f0.x; acc.y += f0.y;
    }
    float sc = rsqrtf(fmaxf((float)deg, 1.f));
    acc.x *= sc; acc.y *= sc;
    reinterpret_cast<float2*>(g_h2)[(size_t)n * 32 + lane] = acc;
}

// ---------------- attention logit sums, both channels (grid.y = channel) ----------------
__global__ __launch_bounds__(128) void k_att(const float* __restrict__ att_w1,
                                             const float* __restrict__ att_b1,
                                             const float* __restrict__ att_w2) {
    __shared__ float Ws[64][32];
    __shared__ float As[8][128];
    __shared__ float b1s[32], w2s[32];
    __shared__ float redbuf[4];

    int tid = threadIdx.x;
    int ch  = blockIdx.y;
    int m0  = blockIdx.x * 128;

    for (int i = tid; i < 64 * 32; i += 128) ((float*)Ws)[i] = att_w1[i];
    if (tid < 32) { b1s[tid] = att_b1[tid]; w2s[tid] = att_w2[tid]; }

    int tx = tid & 7, ty = tid >> 3;
    const float* hsrc = ch ? g_h2 : g_h1;

    int m_load = m0 + tid;
    bool valid = m_load < N_NODES;
    const float4* hrow = reinterpret_cast<const float4*>(hsrc + (size_t)m_load * 64);
    float4 z4 = make_float4(0.f, 0.f, 0.f, 0.f);

    float acc[8][4];
#pragma unroll
    for (int i = 0; i < 8; i++)
#pragma unroll
        for (int j = 0; j < 4; j++) acc[i][j] = 0.f;

    for (int kc = 0; kc < 64; kc += 8) {
        __syncthreads();
        float4 v0 = valid ? hrow[kc >> 2]       : z4;
        float4 v1 = valid ? hrow[(kc >> 2) + 1] : z4;
        As[0][tid] = v0.x; As[1][tid] = v0.y; As[2][tid] = v0.z; As[3][tid] = v0.w;
        As[4][tid] = v1.x; As[5][tid] = v1.y; As[6][tid] = v1.z; As[7][tid] = v1.w;
        __syncthreads();

#pragma unroll
        for (int k = 0; k < 8; k++) {
            float4 a0 = *reinterpret_cast<const float4*>(&As[k][ty * 8]);
            float4 a1 = *reinterpret_cast<const float4*>(&As[k][ty * 8 + 4]);
            float4 b  = *reinterpret_cast<const float4*>(&Ws[kc + k][tx * 4]);
            float a[8] = {a0.x, a0.y, a0.z, a0.w, a1.x, a1.y, a1.z, a1.w};
            float bb[4] = {b.x, b.y, b.z, b.w};
#pragma unroll
            for (int i = 0; i < 8; i++)
#pragma unroll
                for (int j = 0; j < 4; j++) acc[i][j] += a[i] * bb[j];
        }
    }

    float part = 0.f;
#pragma unroll
    for (int i = 0; i < 8; i++) {
        int m = m0 + ty * 8 + i;
        if (m >= N_NODES) continue;
#pragma unroll
        for (int j = 0; j < 4; j++)
            part += fast_tanh(acc[i][j] + b1s[tx * 4 + j]) * w2s[tx * 4 + j];
    }
#pragma unroll
    for (int off = 16; off > 0; off >>= 1)
        part += __shfl_down_sync(0xffffffff, part, off);
    if ((tid & 31) == 0) redbuf[tid >> 5] = part;
    __syncthreads();
    if (tid == 0)
        atomicAdd(&g_wpart[ch][blockIdx.x & 15],
                  redbuf[0] + redbuf[1] + redbuf[2] + redbuf[3]);
}

// ---------------- final: beta softmax, blend, fc2 ----------------
__global__ __launch_bounds__(256) void k_out(const float* __restrict__ fc2_w,
                                             const float* __restrict__ fc2_b,
                                             float* __restrict__ out) {
    __shared__ float4 ws[16 * 16];
    __shared__ float bs[16];

    int tid = threadIdx.x;
    for (int i = tid; i < 16 * 16; i += 256)
        ws[i] = reinterpret_cast<const float4*>(fc2_w)[i];
    if (tid < 16) bs[tid] = fc2_b[tid];
    __syncthreads();

    int n = blockIdx.x * blockDim.x + tid;
    if (n >= N_NODES) return;

    float s0 = 0.f, s1 = 0.f;
#pragma unroll
    for (int i = 0; i < 16; i++) { s0 += g_wpart[0][i]; s1 += g_wpart[1][i]; }
    float m0 = s0 * (1.f / N_NODES);
    float m1 = s1 * (1.f / N_NODES);
    float mx = fmaxf(m0, m1);
    float e0 = expf(m0 - mx), e1 = expf(m1 - mx);
    float inv = 1.f / (e0 + e1);
    float b0 = e0 * inv, b1 = e1 * inv;

    const float4* r1 = reinterpret_cast<const float4*>(g_h1 + (size_t)n * 64);
    const float4* r2 = reinterpret_cast<const float4*>(g_h2 + (size_t)n * 64);
    float4 f[16];
#pragma unroll
    for (int i = 0; i < 16; i++) {
        float4 a = r1[i], b = r2[i];
        f[i] = make_float4(b0 * a.x + b1 * b.x, b0 * a.y + b1 * b.y,
                           b0 * a.z + b1 * b.z, b0 * a.w + b1 * b.w);
    }
    float o[16];
#pragma unroll
    for (int j = 0; j < 16; j++) {
        float acc = bs[j];
#pragma unroll
        for (int i = 0; i < 16; i++) {
            float4 w = ws[j * 16 + i];
            acc += f[i].x * w.x + f[i].y * w.y + f[i].z * w.z + f[i].w * w.w;
        }
        o[j] = acc;
    }
    float4* orow = reinterpret_cast<float4*>(out + (size_t)n * 16);
#pragma unroll
    for (int j = 0; j < 4; j++)
        orow[j] = make_float4(o[j * 4], o[j * 4 + 1], o[j * 4 + 2], o[j * 4 + 3]);
}

// ---------------- launch: fork-join two-stream graph ----------------
extern "C" void kernel_launch(void* const* d_in, const int* in_sizes, int n_in,
                              void* d_out, int out_size)
{
    const float* feat   = (const float*)d_in[0];
    const int*   e_src  = (const int*)  d_in[1];
    const int*   e_dst  = (const int*)  d_in[2];
    const float* fc1_w  = (const float*)d_in[3];
    const float* fc1_b  = (const float*)d_in[4];
    const float* filt_w = (const float*)d_in[5];
    const float* filt_b = (const float*)d_in[6];
    const float* att_w1 = (const float*)d_in[7];
    const float* att_b1 = (const float*)d_in[8];
    const float* att_w2 = (const float*)d_in[9];
    const float* fc2_w  = (const float*)d_in[10];
    const float* fc2_b  = (const float*)d_in[11];
    float* out = (float*)d_out;

    static cudaStream_t s1 = nullptr;
    static cudaEvent_t ev_deg = nullptr, ev_gemm = nullptr;
    if (!s1) {
        cudaStreamCreateWithFlags(&s1, cudaStreamNonBlocking);
        cudaEventCreateWithFlags(&ev_deg,  cudaEventDisableTiming);
        cudaEventCreateWithFlags(&ev_gemm, cudaEventDisableTiming);
    }
    cudaStream_t s0 = (cudaStream_t)0;

    // main chain: degrees -> scan -> CSR
    k_init<<<(N_NODES + 255) / 256, 256, 0, s0>>>();
    k_degree<<<(N_EDGES / 4 + 255) / 256, 256, 0, s0>>>((const int4*)e_src, (const int4*)e_dst);
    cudaEventRecord(ev_deg, s0);

    // side chain: prep -> dual GEMM
    cudaStreamWaitEvent(s1, ev_deg, 0);
    k_prep<<<(N_NODES + 255) / 256, 256, 0, s1>>>(fc1_w, fc1_b, filt_w, filt_b);
    k_gemm<<<(N_NODES + 127) / 128, 256, 0, s1>>>(feat);
    cudaEventRecord(ev_gemm, s1);

    // main chain continues in parallel
    k_scan1<<<NB_SCAN, 256, 0, s0>>>();
    k_scan2<<<1, 512, 0, s0>>>();
    k_scan3<<<(N_NODES + 255) / 256, 256, 0, s0>>>();
    k_csr<<<(N_EDGES + 255) / 256, 256, 0, s0>>>(e_src, e_dst);

    // join: aggregation needs CSR (s0) + xs (gemm, s1)
    cudaStreamWaitEvent(s0, ev_gemm, 0);
    k_agg<<<(N_NODES + 7) / 8, 256, 0, s0>>>();

    // attention for both channels (h1 ready after gemm; h2 after agg)
    k_att<<<dim3((N_NODES + 127) / 128, 2), 128, 0, s0>>>(att_w1, att_b1, att_w2);

    // blend + fc2
    k_out<<<(N_NODES + 255) / 256, 256, 0, s0>>>(fc2_w, fc2_b, out);
}